// round 12
// baseline (speedup 1.0000x reference)
#include <cuda_runtime.h>
#include <cstdint>

// DetectPeaksTM: per-row sliding max (K=301) NMS + top-2 (value, index).
// Persistent double-buffered TMA pipeline: 444 CTAs (3/SM), each CTA streams
// ~14 rows. While row k is reduced/selected from buf[k&1], the TMA for row
// k+1 is in flight into buf[(k+1)&1]; row k+2 is issued right after the
// selection barrier. Candidate-based selection (survivor == max of its
// aligned 128-tile), entirely from smem.

#define NT     8192
#define HALF   150
#define WIN    301
#define NROWS  6144
#define GRID   444          // 148 SMs * 3 CTAs

typedef unsigned long long u64;
typedef unsigned int u32;

__device__ __forceinline__ u32 absbits(float f) {
    return __float_as_uint(f) & 0x7fffffffu;
}
__device__ __forceinline__ u64 umax64(u64 a, u64 b) { return a > b ? a : b; }
__device__ __forceinline__ u64 shfl_xor_u64(u64 v, int d) {
    u32 lo = (u32)v, hi = (u32)(v >> 32);
    lo = __shfl_xor_sync(0xffffffffu, lo, d);
    hi = __shfl_xor_sync(0xffffffffu, hi, d);
    return ((u64)hi << 32) | lo;
}
__device__ __forceinline__ u32 smem_addr(const void* p) {
    u32 a;
    asm("{ .reg .u64 t; cvta.to.shared.u64 t, %1; cvt.u32.u64 %0, t; }"
        : "=r"(a) : "l"(p));
    return a;
}
__device__ __forceinline__ void mbar_wait(u32 mb, u32 parity) {
    u32 done;
    asm volatile(
        "{\n\t.reg .pred p;\n\t"
        "mbarrier.try_wait.parity.acquire.cta.shared::cta.b64 p, [%1], %2;\n\t"
        "selp.b32 %0, 1, 0, p;\n\t}"
        : "=r"(done) : "r"(mb), "r"(parity) : "memory");
    while (!done) {
        asm volatile(
            "{\n\t.reg .pred p;\n\t"
            "mbarrier.try_wait.parity.acquire.cta.shared::cta.b64 p, [%1], %2, 0x989680;\n\t"
            "selp.b32 %0, 1, 0, p;\n\t}"
            : "=r"(done) : "r"(mb), "r"(parity) : "memory");
    }
}
__device__ __forceinline__ void tma_row(u32 dst, const float* src, u32 mb) {
    asm volatile("mbarrier.arrive.expect_tx.shared.b64 _, [%0], %1;"
                 :: "r"(mb), "r"(NT * 4) : "memory");
    asm volatile("cp.async.bulk.shared::cta.global.mbarrier::complete_tx::bytes "
                 "[%0], [%1], %2, [%3];"
                 :: "r"(dst), "l"(src), "r"(NT * 4), "r"(mb) : "memory");
}

// First index > bound inside tile whose absbits == val, or -1.
__device__ __forceinline__ int find_next(u32 em, int tile, int bound, int lane) {
    int base = tile * 128 + lane * 4;
    int rel = bound - base;                  // element j excluded iff j <= rel
    u32 emm = em;
    if (rel >= 3) emm = 0;
    else if (rel >= 0) emm &= (0xFu << (rel + 1));
    u32 bl = __ballot_sync(0xffffffffu, emm != 0);
    if (!bl) return -1;
    int lf = __ffs((int)bl) - 1;
    u32 pk = __shfl_sync(0xffffffffu, emm, lf);
    return tile * 128 + lf * 4 + (__ffs((int)pk) - 1);
}

__device__ void select_row(const float* __restrict__ buf,
                           const u32* __restrict__ tileMax,
                           float* __restrict__ out, int row, int lane) {
    const u32 FULL = 0xffffffffu;
    const float4* sb = (const float4*)buf;

    u64 keys[2];
#pragma unroll
    for (int q = 0; q < 2; q++) {
        int t = lane + 32 * q;
        keys[q] = ((u64)tileMax[t] << 32) | (u32)(~(u32)(t * 128));
    }
    u64 pend = 0;
    int pendIdx = -1;

    float rv0 = 0.0f, rv1 = 0.0f;
    int   ri0 = 0,    ri1 = 0;
    int found = 0;

    for (int it = 0; it < 192 && found < 2; it++) {
        u64 best = umax64(umax64(keys[0], keys[1]), pend);
#pragma unroll
        for (int s = 16; s > 0; s >>= 1) best = umax64(best, shfl_xor_u64(best, s));
        if (best == 0ull) break;

        bool wasPend = (best == pend && pend != 0ull);
        if (wasPend) pend = 0;
        if (keys[0] == best) keys[0] = 0;
        if (keys[1] == best) keys[1] = 0;

        u32 val = (u32)(best >> 32);
        int tile, idxV;
        if (wasPend) { idxV = pendIdx; tile = idxV >> 7; }
        else         { tile = (int)((~(u32)(best & 0xffffffffull)) >> 7); idxV = -1; }

        float4 tv = sb[tile * 32 + lane];
        u32 em = (u32)(absbits(tv.x) == val)        |
                 ((u32)(absbits(tv.y) == val) << 1) |
                 ((u32)(absbits(tv.z) == val) << 2) |
                 ((u32)(absbits(tv.w) == val) << 3);
        if (!wasPend) idxV = find_next(em, tile, tile * 128 - 1, lane);
        int nxt = find_next(em, tile, idxV, lane);
        if (nxt >= 0) { pend = ((u64)val << 32) | (u32)(~(u32)nxt); pendIdx = nxt; }

        int lo = max(idxV - HALF, 0);
        int hi = min(idxV + HALF, NT - 1);
        int ta = lo >> 7, tb = hi >> 7;
        int t = ta + lane;
        u32 tm = (t <= tb) ? tileMax[t] : 0u;
        u32 bound = __reduce_max_sync(FULL, tm);

        bool accept = (bound <= val);
        if (!accept) {
            bool fullt = (t <= tb) && (t * 128 >= lo) && (t * 128 + 127 <= hi);
            if (__reduce_max_sync(FULL, fullt ? tm : 0u) > val) continue;
            u32 mbx = 0;
            int base = idxV - HALF;
#pragma unroll
            for (int rr = 0; rr < 10; rr++) {
                int off = lane + 32 * rr;
                int p = min(max(base + off, 0), NT - 1);
                u32 xb = absbits(buf[p]);
                if (off < WIN) mbx = max(mbx, xb);
            }
            if (__reduce_max_sync(FULL, mbx) > val) continue;
            accept = true;
        }

        if (found == 0) { rv0 = __uint_as_float(val); ri0 = idxV; }
        else            { rv1 = __uint_as_float(val); ri1 = idxV; }
        found++;
    }

    if (lane == 0) {
        if (found < 2) {
            rv1 = 0.0f;
            ri1 = (found >= 1 && ri0 == 0) ? 1 : 0;
        }
        out[row * 2 + 0] = rv0;
        out[row * 2 + 1] = rv1;
        out[(size_t)NROWS * 2 + row * 2 + 0] = (float)ri0;
        out[(size_t)NROWS * 2 + row * 2 + 1] = (float)ri1;
    }
}

__global__ void __launch_bounds__(256)
detect_peaks_kernel(const float* __restrict__ x, float* __restrict__ out) {
    extern __shared__ char smraw[];
    float* buf0 = (float*)smraw;                         // 32 KB
    float* buf1 = buf0 + NT;                             // 32 KB
    u32*   tileMax = (u32*)(smraw + 2 * NT * 4);         // 256 B
    u64*   mbar    = (u64*)(smraw + 2 * NT * 4 + 256);   // 16 B

    const int bid  = blockIdx.x;
    const int tid  = threadIdx.x;
    const int lane = tid & 31;
    const int warp = tid >> 5;
    const u32 FULL = 0xffffffffu;

    const u32 mb0 = smem_addr(&mbar[0]);
    const u32 mb1 = smem_addr(&mbar[1]);
    const u32 db0 = smem_addr(buf0);
    const u32 db1 = smem_addr(buf1);

    const int nIter = (NROWS - bid + GRID - 1) / GRID;

    if (tid == 0) {
        asm volatile("mbarrier.init.shared.b64 [%0], 1;" :: "r"(mb0) : "memory");
        asm volatile("mbarrier.init.shared.b64 [%0], 1;" :: "r"(mb1) : "memory");
    }
    __syncthreads();

    if (tid == 0) {
        tma_row(db0, x + (size_t)bid * NT, mb0);
        if (nIter > 1)
            tma_row(db1, x + (size_t)(bid + GRID) * NT, mb1);
    }

    u32 ph0 = 0, ph1 = 0;

    for (int k = 0; k < nIter; k++) {
        const int b = k & 1;
        const int row = bid + k * GRID;
        float* buf = b ? buf1 : buf0;

        if (b) { mbar_wait(mb1, ph1); ph1 ^= 1; }
        else   { mbar_wait(mb0, ph0); ph0 ^= 1; }

        // tile maxima
        const float4* sb = (const float4*)buf;
#pragma unroll
        for (int q = 0; q < 8; q++) {
            float4 v = sb[tid + 256 * q];
            float m01 = fmaxf(fabsf(v.x), fabsf(v.y));
            float m23 = fmaxf(fabsf(v.z), fabsf(v.w));
            float m   = fmaxf(m01, m23);
            u32 m1 = __reduce_max_sync(FULL, __float_as_uint(m));
            if (lane == 0) tileMax[warp + 8 * q] = m1;
        }
        __syncthreads();

        if (warp == 0)
            select_row(buf, tileMax, out, row, lane);
        __syncthreads();

        // refill this buffer with row k+2 (all reads of buf done)
        if (tid == 0 && k + 2 < nIter)
            tma_row(b ? db1 : db0, x + (size_t)(bid + (k + 2) * GRID) * NT,
                    b ? mb1 : mb0);
    }
}

extern "C" void kernel_launch(void* const* d_in, const int* in_sizes, int n_in,
                              void* d_out, int out_size) {
    const float* x = (const float*)d_in[0];
    float* out = (float*)d_out;

    size_t smem = (size_t)2 * NT * 4 + 256 + 16;   // 65808 B
    cudaFuncSetAttribute(detect_peaks_kernel,
                         cudaFuncAttributeMaxDynamicSharedMemorySize, (int)smem);
    detect_peaks_kernel<<<GRID, 256, smem>>>(x, out);
}